// round 4
// baseline (speedup 1.0000x reference)
#include <cuda_runtime.h>
#include <cuda_bf16.h>

#define IMG 256
#define TILE 32
#define HALO 3
#define SW (TILE + 2 * HALO)      // 38
#define SPITCH 40                 // padded pitch for x tile

__global__ __launch_bounds__(256, 5)
void AdaptiveGaussianFilter_66675072303489_kernel(
    const float* __restrict__ x,
    const float* __restrict__ sigma,
    float* __restrict__ out)
{
    __shared__ float  sm[SW][SPITCH];      // raw x halo tile (6.1 KB)
    __shared__ float4 qs[SW][TILE];        // per-(row,col) quartets (19 KB)

    const int ch = blockIdx.z;
    const int x0 = blockIdx.x * TILE;
    const int y0 = blockIdx.y * TILE;

    const float* xc = x     + (size_t)ch * IMG * IMG;
    const float* sc = sigma + (size_t)ch * IMG * IMG;
    float*       oc = out   + (size_t)ch * IMG * IMG;

    const int tid = threadIdx.y * 32 + threadIdx.x;
    const int lx  = threadIdx.x;
    const int ly0 = threadIdx.y * 4;

    // Preload 4 sigma values (global latency overlaps the tile staging)
    float sv[4];
    #pragma unroll
    for (int k = 0; k < 4; k++)
        sv[k] = sc[(y0 + ly0 + k) * IMG + (x0 + lx)];

    // ---- Pass 0: stage x halo tile (reflect only on border blocks) ----
    const bool interior = (blockIdx.x != 0) & (blockIdx.x != 7) &
                          (blockIdx.y != 0) & (blockIdx.y != 7);
    if (interior) {
        const float* src = xc + (y0 - HALO) * IMG + (x0 - HALO);
        #pragma unroll
        for (int i = tid; i < SW * SW; i += 256) {
            int sy = i / SW;
            int sx = i - sy * SW;
            sm[sy][sx] = src[sy * IMG + sx];
        }
    } else {
        #pragma unroll
        for (int i = tid; i < SW * SW; i += 256) {
            int sy = i / SW;
            int sx = i - sy * SW;
            int gy = y0 + sy - HALO;
            int gx = x0 + sx - HALO;
            gy = (gy < 0) ? -gy : ((gy > IMG - 1) ? 2 * (IMG - 1) - gy : gy);
            gx = (gx < 0) ? -gx : ((gx > IMG - 1) ? 2 * (IMG - 1) - gx : gx);
            sm[sy][sx] = xc[gy * IMG + gx];
        }
    }
    __syncthreads();

    // ---- Pass 1: build sigma-independent quartets, shared across rows ----
    // quartet(row, col): m=w3, a=w2+w4, b=w1+w5, c=w0+w6 over sm[row][col..col+6]
    // 38 rows x 8 strips of 4 consecutive columns = 304 work items.
    for (int j = tid; j < SW * 8; j += 256) {
        const int row = j >> 3;
        const int c0  = (j & 7) * 4;
        float w[10];
        #pragma unroll
        for (int i = 0; i < 10; i++)
            w[i] = sm[row][c0 + i];
        #pragma unroll
        for (int i = 0; i < 4; i++) {
            qs[row][c0 + i] = make_float4(w[i + 3],
                                          w[i + 2] + w[i + 4],
                                          w[i + 1] + w[i + 5],
                                          w[i]     + w[i + 6]);
        }
    }
    __syncthreads();

    // ---- Pass 2: rolling 7-row quartet window, 10 x LDS.128 per 4 pixels ----
    float4 q[7];
    #pragma unroll
    for (int i = 0; i < 7; i++)
        q[i] = qs[ly0 + i][lx];

    #pragma unroll
    for (int k = 0; k < 4; k++) {
        float t  = __expf(-0.5f * sv[k] * sv[k]);
        float t2 = t * t;
        float t4 = t2 * t2;
        float t9 = t4 * t4 * t;
        float S  = fmaf(2.0f, t + t4 + t9, 1.0f);

        float h[7];
        #pragma unroll
        for (int r = 0; r < 7; r++) {
            const int s_ = (k + r) % 7;      // compile-time after unroll
            float hh = fmaf(t,  q[s_].y, q[s_].x);
            hh       = fmaf(t4, q[s_].z, hh);
            h[r]     = fmaf(t9, q[s_].w, hh);
        }
        float acc = fmaf(t,  h[2] + h[4], h[3]);
        acc       = fmaf(t4, h[1] + h[5], acc);
        acc       = fmaf(t9, h[0] + h[6], acc);

        oc[(y0 + ly0 + k) * IMG + (x0 + lx)] = __fdividef(acc, S * S);

        if (k < 3)
            q[k] = qs[ly0 + 7 + k][lx];      // slide into retired slot
    }
}

extern "C" void kernel_launch(void* const* d_in, const int* in_sizes, int n_in,
                              void* d_out, int out_size)
{
    const float* x     = (const float*)d_in[0];
    const float* sigma = (const float*)d_in[1];
    float*       out   = (float*)d_out;

    dim3 block(32, 8, 1);
    dim3 grid(IMG / TILE, IMG / TILE, 16 * 3);
    AdaptiveGaussianFilter_66675072303489_kernel<<<grid, block>>>(x, sigma, out);
}

// round 6
// speedup vs baseline: 1.7539x; 1.7539x over previous
#include <cuda_runtime.h>
#include <cuda_bf16.h>

#define IMG 256
#define TILE_W 32
#define TILE_H 64
#define HALO 3
#define SH (TILE_H + 2 * HALO)    // 70 rows
#define SWD (TILE_W + 2 * HALO)   // 38 cols
#define SPITCH 40                 // padded pitch

__device__ __forceinline__ int reflect(int v) {
    v = (v < 0) ? -v : v;
    return (v > IMG - 1) ? 2 * (IMG - 1) - v : v;
}

__global__ __launch_bounds__(256, 5)
void AdaptiveGaussianFilter_66675072303489_kernel(
    const float* __restrict__ x,
    const float* __restrict__ sigma,
    float* __restrict__ out)
{
    __shared__ float sm[SH][SPITCH];     // 11.2 KB

    const int ch = blockIdx.z;
    const int x0 = blockIdx.x * TILE_W;
    const int y0 = blockIdx.y * TILE_H;

    const float* xc = x     + (size_t)ch * IMG * IMG;
    const float* sc = sigma + (size_t)ch * IMG * IMG;
    float*       oc = out   + (size_t)ch * IMG * IMG;

    const int lane = threadIdx.x;        // 0..31
    const int warp = threadIdx.y;        // 0..7

    // ---- Halo fill: warp w owns rows w, w+8, ...  (no division, no mod) ----
    const bool interior = (blockIdx.x != 0) & (blockIdx.x != 7) &
                          (blockIdx.y != 0) & (blockIdx.y != 3);
    if (interior) {
        const float* src = xc + (y0 - HALO) * IMG + (x0 - HALO);
        #pragma unroll
        for (int i = 0; i < 8; i++) {
            const int r = warp + 8 * i;
            const float* srow = src + r * IMG;
            sm[r][lane] = srow[lane];
            if (lane < SWD - 32) sm[r][lane + 32] = srow[lane + 32];
        }
        if (warp < SH - 64) {
            const int r = warp + 64;
            const float* srow = src + r * IMG;
            sm[r][lane] = srow[lane];
            if (lane < SWD - 32) sm[r][lane + 32] = srow[lane + 32];
        }
    } else {
        // Column reflect hoisted (lane-only); row reflect per iteration.
        const int gx1 = reflect(x0 + lane - HALO);
        const int gx2 = reflect(x0 + lane + 32 - HALO);
        #pragma unroll
        for (int i = 0; i < 8; i++) {
            const int r  = warp + 8 * i;
            const int gy = reflect(y0 + r - HALO);
            sm[r][lane] = xc[gy * IMG + gx1];
            if (lane < SWD - 32) sm[r][lane + 32] = xc[gy * IMG + gx2];
        }
        if (warp < SH - 64) {
            const int r  = warp + 64;
            const int gy = reflect(y0 + r - HALO);
            sm[r][lane] = xc[gy * IMG + gx1];
            if (lane < SWD - 32) sm[r][lane + 32] = xc[gy * IMG + gx2];
        }
    }
    __syncthreads();

    // ---- Per-thread: 8 vertically consecutive pixels, rolling quartet window ----
    const int ly0 = warp * 8;
    const float* sp = sc + (y0 + ly0) * IMG + (x0 + lane);
    float*       op = oc + (y0 + ly0) * IMG + (x0 + lane);

    // quartets: m=w3, a=w2+w4, b=w1+w5, c=w0+w6
    float m[7], a[7], b[7], c[7];
    #pragma unroll
    for (int i = 0; i < 7; i++) {
        const float* row = &sm[ly0 + i][lane];
        m[i] = row[3];
        a[i] = row[2] + row[4];
        b[i] = row[1] + row[5];
        c[i] = row[0] + row[6];
    }

    float s = sp[0];                      // sigma prefetch (1 ahead)
    #pragma unroll
    for (int k = 0; k < 8; k++) {
        float s_next = (k < 7) ? sp[(k + 1) * IMG] : 0.0f;

        float t  = __expf(-0.5f * s * s);
        float t2 = t * t;
        float t4 = t2 * t2;
        float t9 = t4 * t4 * t;
        float S  = fmaf(2.0f, t + t4 + t9, 1.0f);

        // h_r = m + t*a + t4*b + t9*c ; acc = sum over rows, u = [t9,t4,t,1,t,t4,t9]
        float acc0, acc1;
        {
            const int s0 = k % 7;         // u = t9
            float h = fmaf(t, a[s0], m[s0]); h = fmaf(t4, b[s0], h); h = fmaf(t9, c[s0], h);
            acc0 = h * t9;
        }
        {
            const int s1 = (k + 1) % 7;   // u = t4
            float h = fmaf(t, a[s1], m[s1]); h = fmaf(t4, b[s1], h); h = fmaf(t9, c[s1], h);
            acc1 = h * t4;
        }
        {
            const int s2 = (k + 2) % 7;   // u = t
            float h = fmaf(t, a[s2], m[s2]); h = fmaf(t4, b[s2], h); h = fmaf(t9, c[s2], h);
            acc0 = fmaf(h, t, acc0);
        }
        {
            const int s3 = (k + 3) % 7;   // u = 1
            float h = fmaf(t, a[s3], m[s3]); h = fmaf(t4, b[s3], h); h = fmaf(t9, c[s3], h);
            acc1 += h;
        }
        {
            const int s4 = (k + 4) % 7;   // u = t
            float h = fmaf(t, a[s4], m[s4]); h = fmaf(t4, b[s4], h); h = fmaf(t9, c[s4], h);
            acc0 = fmaf(h, t, acc0);
        }
        {
            const int s5 = (k + 5) % 7;   // u = t4
            float h = fmaf(t, a[s5], m[s5]); h = fmaf(t4, b[s5], h); h = fmaf(t9, c[s5], h);
            acc1 = fmaf(h, t4, acc1);
        }
        {
            const int s6 = (k + 6) % 7;   // u = t9
            float h = fmaf(t, a[s6], m[s6]); h = fmaf(t4, b[s6], h); h = fmaf(t9, c[s6], h);
            acc0 = fmaf(h, t9, acc0);
        }

        op[k * IMG] = __fdividef(acc0 + acc1, S * S);

        // Slide: bring row ly0+7+k into retired slot (k % 7)
        if (k < 7) {
            const float* row = &sm[ly0 + 7 + k][lane];
            const int d = k % 7;
            m[d] = row[3];
            a[d] = row[2] + row[4];
            b[d] = row[1] + row[5];
            c[d] = row[0] + row[6];
        }
        s = s_next;
    }
}

extern "C" void kernel_launch(void* const* d_in, const int* in_sizes, int n_in,
                              void* d_out, int out_size)
{
    const float* x     = (const float*)d_in[0];
    const float* sigma = (const float*)d_in[1];
    float*       out   = (float*)d_out;

    dim3 block(32, 8, 1);
    dim3 grid(IMG / TILE_W, IMG / TILE_H, 16 * 3);   // 8 x 4 x 48 = 1536
    AdaptiveGaussianFilter_66675072303489_kernel<<<grid, block>>>(x, sigma, out);
}

// round 7
// speedup vs baseline: 1.9620x; 1.1187x over previous
#include <cuda_runtime.h>

#define IMG 256
#define TW 64
#define TH 32
#define PR (TH + 6)   // 38 quartet-plane rows

typedef unsigned long long u64;

// ---- packed f32x2 helpers (sm_103a FFMA2 path, PTX-only) ----
__device__ __forceinline__ u64 pk2(float lo, float hi) {
    u64 r; asm("mov.b64 %0, {%1,%2};" : "=l"(r) : "f"(lo), "f"(hi)); return r;
}
__device__ __forceinline__ void upk2(float& lo, float& hi, u64 p) {
    asm("mov.b64 {%0,%1}, %2;" : "=f"(lo), "=f"(hi) : "l"(p));
}
__device__ __forceinline__ u64 f2fma(u64 a, u64 b, u64 c) {
    u64 d; asm("fma.rn.f32x2 %0,%1,%2,%3;" : "=l"(d) : "l"(a), "l"(b), "l"(c)); return d;
}
__device__ __forceinline__ u64 f2mul(u64 a, u64 b) {
    u64 d; asm("mul.rn.f32x2 %0,%1,%2;" : "=l"(d) : "l"(a), "l"(b)); return d;
}
__device__ __forceinline__ u64 f2add(u64 a, u64 b) {
    u64 d; asm("add.rn.f32x2 %0,%1,%2;" : "=l"(d) : "l"(a), "l"(b)); return d;
}
__device__ __forceinline__ float ex2f(float x) {
    float r; asm("ex2.approx.f32 %0, %1;" : "=f"(r) : "f"(x)); return r;
}
__device__ __forceinline__ float rcpf(float x) {
    float r; asm("rcp.approx.f32 %0, %1;" : "=f"(r) : "f"(x)); return r;
}

__device__ __forceinline__ int reflect(int v) {
    v = (v < 0) ? -v : v;
    return (v > IMG - 1) ? 2 * (IMG - 1) - v : v;
}

__global__ __launch_bounds__(256, 4)
void AdaptiveGaussianFilter_66675072303489_kernel(
    const float* __restrict__ x,
    const float* __restrict__ sigma,
    float* __restrict__ out)
{
    // Planar quartet planes: m=w0, a=w-1+w+1, b=w-2+w+2, c=w-3+w+3 (38.9 KB)
    __shared__ __align__(16) float qm[PR][TW];
    __shared__ __align__(16) float qa[PR][TW];
    __shared__ __align__(16) float qb[PR][TW];
    __shared__ __align__(16) float qc[PR][TW];

    const int ch = blockIdx.z;
    const int x0 = blockIdx.x * TW;
    const int y0 = blockIdx.y * TH;

    const float* xc = x     + (size_t)ch * IMG * IMG;
    const float* sc = sigma + (size_t)ch * IMG * IMG;
    float*       oc = out   + (size_t)ch * IMG * IMG;

    const int tx  = threadIdx.x;
    const int ty  = threadIdx.y;
    const int tid = ty * 32 + tx;

    // ---- Pass 1: build quartet planes straight from gmem ----
    const bool interior = (blockIdx.x != 0) & (blockIdx.x != 3) &
                          (blockIdx.y != 0) & (blockIdx.y != 7);
    #pragma unroll
    for (int it = 0; it < 3; it++) {
        int idx = tid + it * 256;
        if (idx < PR * 16) {                 // 38 rows x 16 strips of 4 cols
            int r  = idx >> 4;
            int c0 = (idx & 15) << 2;
            float w[10];                     // x[x0+c0-3 .. x0+c0+6]
            if (interior) {
                const float* src = xc + (y0 + r - 3) * IMG + (x0 + c0 - 3);
                #pragma unroll
                for (int i = 0; i < 10; i++) w[i] = src[i];
            } else {
                const float* srow = xc + reflect(y0 + r - 3) * IMG;
                #pragma unroll
                for (int i = 0; i < 10; i++) w[i] = srow[reflect(x0 + c0 - 3 + i)];
            }
            *(float4*)&qm[r][c0] = make_float4(w[3], w[4], w[5], w[6]);
            *(float4*)&qa[r][c0] = make_float4(w[2]+w[4], w[3]+w[5], w[4]+w[6], w[5]+w[7]);
            *(float4*)&qb[r][c0] = make_float4(w[1]+w[5], w[2]+w[6], w[3]+w[7], w[4]+w[8]);
            *(float4*)&qc[r][c0] = make_float4(w[0]+w[6], w[1]+w[7], w[2]+w[8], w[3]+w[9]);
        }
    }
    __syncthreads();

    // ---- Pass 2: thread = 2 adjacent cols x 4 rows, all math packed ----
    const int c2  = tx << 1;                 // 0..62
    const int ly0 = ty << 2;                 // 0..28

    const u64 TWO2 = pk2(2.0f, 2.0f);
    const u64 ONE2 = pk2(1.0f, 1.0f);
    const u64 NHL  = pk2(-0.72134752f, -0.72134752f);   // -0.5*log2(e)

    // rolling window: m,a,b packs for rows ly0..ly0+6 (c JIT-loaded)
    u64 wm[7], wa[7], wb[7];
    #pragma unroll
    for (int i = 0; i < 7; i++) {
        wm[i] = *(const u64*)&qm[ly0 + i][c2];
        wa[i] = *(const u64*)&qa[ly0 + i][c2];
        wb[i] = *(const u64*)&qb[ly0 + i][c2];
    }

    const float* sp = sc + (y0 + ly0) * IMG + x0 + c2;
    float*       op = oc + (y0 + ly0) * IMG + x0 + c2;
    u64 sg = *(const u64*)sp;                // packed sigma pair, prefetched

    // H(d): per-row horizontal combine, c component JIT from smem (last operand)
    #define HD(d) ({ const int s_ = (k + (d)) % 7;                              \
                     u64 h_ = f2fma(t,  wa[s_], wm[s_]);                        \
                     h_     = f2fma(t4, wb[s_], h_);                            \
                     f2fma(t9, *(const u64*)&qc[ly0 + k + (d)][c2], h_); })

    #pragma unroll
    for (int k = 0; k < 4; k++) {
        u64 sg_next = (k < 3) ? *(const u64*)(sp + (k + 1) * IMG) : 0ull;

        // packed t = exp(-sigma^2/2) and powers
        u64 z = f2mul(sg, sg);
        z = f2mul(z, NHL);
        float zl, zh; upk2(zl, zh, z);
        u64 t  = pk2(ex2f(zl), ex2f(zh));
        u64 t2 = f2mul(t, t);
        u64 t4 = f2mul(t2, t2);
        u64 t9 = f2mul(f2mul(t4, t4), t);
        u64 S  = f2fma(TWO2, f2add(f2add(t, t4), t9), ONE2);

        // vertical combine, symmetric pairs: u = [t9,t4,t,1,t,t4,t9]
        u64 acc = HD(3);
        acc = f2fma(t,  f2add(HD(2), HD(4)), acc);
        acc = f2fma(t4, f2add(HD(1), HD(5)), acc);
        acc = f2fma(t9, f2add(HD(0), HD(6)), acc);

        // out = acc / S^2 (packed), 64-bit store of both columns
        u64 SS = f2mul(S, S);
        float sl, sh; upk2(sl, sh, SS);
        float al, ah; upk2(al, ah, acc);
        *(u64*)(op + k * IMG) = pk2(al * rcpf(sl), ah * rcpf(sh));

        // slide window: row ly0+7+k into retired slot k
        if (k < 3) {
            wm[k] = *(const u64*)&qm[ly0 + 7 + k][c2];
            wa[k] = *(const u64*)&qa[ly0 + 7 + k][c2];
            wb[k] = *(const u64*)&qb[ly0 + 7 + k][c2];
        }
        sg = sg_next;
    }
    #undef HD
}

extern "C" void kernel_launch(void* const* d_in, const int* in_sizes, int n_in,
                              void* d_out, int out_size)
{
    const float* x     = (const float*)d_in[0];
    const float* sigma = (const float*)d_in[1];
    float*       out   = (float*)d_out;

    dim3 block(32, 8, 1);
    dim3 grid(IMG / TW, IMG / TH, 16 * 3);   // 4 x 8 x 48 = 1536
    AdaptiveGaussianFilter_66675072303489_kernel<<<grid, block>>>(x, sigma, out);
}

// round 8
// speedup vs baseline: 2.0667x; 1.0533x over previous
#include <cuda_runtime.h>

#define IMG 256
#define TW 64
#define TH 32
#define PR (TH + 6)   // 38 quartet-plane rows

typedef unsigned long long u64;

// ---- packed f32x2 helpers (sm_103a FFMA2 path, PTX-only) ----
__device__ __forceinline__ u64 pk2(float lo, float hi) {
    u64 r; asm("mov.b64 %0, {%1,%2};" : "=l"(r) : "f"(lo), "f"(hi)); return r;
}
__device__ __forceinline__ void upk2(float& lo, float& hi, u64 p) {
    asm("mov.b64 {%0,%1}, %2;" : "=f"(lo), "=f"(hi) : "l"(p));
}
__device__ __forceinline__ u64 f2fma(u64 a, u64 b, u64 c) {
    u64 d; asm("fma.rn.f32x2 %0,%1,%2,%3;" : "=l"(d) : "l"(a), "l"(b), "l"(c)); return d;
}
__device__ __forceinline__ u64 f2mul(u64 a, u64 b) {
    u64 d; asm("mul.rn.f32x2 %0,%1,%2;" : "=l"(d) : "l"(a), "l"(b)); return d;
}
__device__ __forceinline__ u64 f2add(u64 a, u64 b) {
    u64 d; asm("add.rn.f32x2 %0,%1,%2;" : "=l"(d) : "l"(a), "l"(b)); return d;
}
__device__ __forceinline__ float ex2f(float x) {
    float r; asm("ex2.approx.f32 %0, %1;" : "=f"(r) : "f"(x)); return r;
}
__device__ __forceinline__ float rcpf(float x) {
    float r; asm("rcp.approx.f32 %0, %1;" : "=f"(r) : "f"(x)); return r;
}

__device__ __forceinline__ int reflect(int v) {
    v = (v < 0) ? -v : v;
    return (v > IMG - 1) ? 2 * (IMG - 1) - v : v;
}

__global__ __launch_bounds__(256, 3)
void AdaptiveGaussianFilter_66675072303489_kernel(
    const float* __restrict__ x,
    const float* __restrict__ sigma,
    float* __restrict__ out)
{
    // Planar quartet planes: m=w0, a=w-1+w+1, b=w-2+w+2, c=w-3+w+3 (38.9 KB)
    __shared__ __align__(16) float qm[PR][TW];
    __shared__ __align__(16) float qa[PR][TW];
    __shared__ __align__(16) float qb[PR][TW];
    __shared__ __align__(16) float qc[PR][TW];

    const int ch = blockIdx.z;
    const int x0 = blockIdx.x * TW;
    const int y0 = blockIdx.y * TH;

    const float* xc = x     + (size_t)ch * IMG * IMG;
    const float* sc = sigma + (size_t)ch * IMG * IMG;
    float*       oc = out   + (size_t)ch * IMG * IMG;

    const int tx  = threadIdx.x;
    const int ty  = threadIdx.y;
    const int tid = ty * 32 + tx;

    const int c2  = tx << 1;                 // 0..62
    const int ly0 = ty << 2;                 // 0..28

    // Preload all 4 sigma pairs up front (fully hides LDG latency)
    const float* sp = sc + (y0 + ly0) * IMG + x0 + c2;
    u64 sg0 = *(const u64*)(sp);
    u64 sg1 = *(const u64*)(sp + IMG);
    u64 sg2 = *(const u64*)(sp + 2 * IMG);
    u64 sg3 = *(const u64*)(sp + 3 * IMG);

    // ---- Pass 1: build quartet planes straight from gmem ----
    const bool interior = (blockIdx.x != 0) & (blockIdx.x != 3) &
                          (blockIdx.y != 0) & (blockIdx.y != 7);
    #pragma unroll
    for (int it = 0; it < 3; it++) {
        int idx = tid + it * 256;
        if (idx < PR * 16) {                 // 38 rows x 16 strips of 4 cols
            int r  = idx >> 4;
            int c0 = (idx & 15) << 2;
            float w[10];                     // x[x0+c0-3 .. x0+c0+6]
            if (interior) {
                const float* src = xc + (y0 + r - 3) * IMG + (x0 + c0 - 3);
                #pragma unroll
                for (int i = 0; i < 10; i++) w[i] = src[i];
            } else {
                const float* srow = xc + reflect(y0 + r - 3) * IMG;
                #pragma unroll
                for (int i = 0; i < 10; i++) w[i] = srow[reflect(x0 + c0 - 3 + i)];
            }
            *(float4*)&qm[r][c0] = make_float4(w[3], w[4], w[5], w[6]);
            *(float4*)&qa[r][c0] = make_float4(w[2]+w[4], w[3]+w[5], w[4]+w[6], w[5]+w[7]);
            *(float4*)&qb[r][c0] = make_float4(w[1]+w[5], w[2]+w[6], w[3]+w[7], w[4]+w[8]);
            *(float4*)&qc[r][c0] = make_float4(w[0]+w[6], w[1]+w[7], w[2]+w[8], w[3]+w[9]);
        }
    }
    __syncthreads();

    // ---- Pass 2: thread = 2 adjacent cols x 4 rows, full 4-plane window ----
    const u64 TWO2 = pk2(2.0f, 2.0f);
    const u64 ONE2 = pk2(1.0f, 1.0f);
    const u64 NHL  = pk2(-0.72134752f, -0.72134752f);   // -0.5*log2(e)

    u64 wm[7], wa[7], wb[7], wc[7];
    #pragma unroll
    for (int i = 0; i < 7; i++) {
        wm[i] = *(const u64*)&qm[ly0 + i][c2];
        wa[i] = *(const u64*)&qa[ly0 + i][c2];
        wb[i] = *(const u64*)&qb[ly0 + i][c2];
        wc[i] = *(const u64*)&qc[ly0 + i][c2];
    }

    float* op = oc + (y0 + ly0) * IMG + x0 + c2;

    // H(d): per-row horizontal combine, all operands register-resident
    #define HD(d) ({ const int s_ = (k + (d)) % 7;                              \
                     u64 h_ = f2fma(t,  wa[s_], wm[s_]);                        \
                     h_     = f2fma(t4, wb[s_], h_);                            \
                     f2fma(t9, wc[s_], h_); })

    #pragma unroll
    for (int k = 0; k < 4; k++) {
        const u64 sg = (k == 0) ? sg0 : (k == 1) ? sg1 : (k == 2) ? sg2 : sg3;

        // packed t = exp(-sigma^2/2) and powers
        u64 z = f2mul(sg, sg);
        z = f2mul(z, NHL);
        float zl, zh; upk2(zl, zh, z);
        u64 t  = pk2(ex2f(zl), ex2f(zh));
        u64 t2 = f2mul(t, t);
        u64 t4 = f2mul(t2, t2);
        u64 t9 = f2mul(f2mul(t4, t4), t);
        u64 S  = f2fma(TWO2, f2add(f2add(t, t4), t9), ONE2);

        // vertical combine, symmetric pairs: u = [t9,t4,t,1,t,t4,t9]
        u64 acc = HD(3);
        acc = f2fma(t,  f2add(HD(2), HD(4)), acc);
        acc = f2fma(t4, f2add(HD(1), HD(5)), acc);
        acc = f2fma(t9, f2add(HD(0), HD(6)), acc);

        // out = acc / S^2 (packed halves via scalar rcp), 64-bit store
        u64 SS = f2mul(S, S);
        float sl, sh; upk2(sl, sh, SS);
        float al, ah; upk2(al, ah, acc);
        *(u64*)(op + k * IMG) = pk2(al * rcpf(sl), ah * rcpf(sh));

        // slide window: row ly0+7+k into retired slot k (consumed next iter)
        if (k < 3) {
            wm[k] = *(const u64*)&qm[ly0 + 7 + k][c2];
            wa[k] = *(const u64*)&qa[ly0 + 7 + k][c2];
            wb[k] = *(const u64*)&qb[ly0 + 7 + k][c2];
            wc[k] = *(const u64*)&qc[ly0 + 7 + k][c2];
        }
    }
    #undef HD
}

extern "C" void kernel_launch(void* const* d_in, const int* in_sizes, int n_in,
                              void* d_out, int out_size)
{
    const float* x     = (const float*)d_in[0];
    const float* sigma = (const float*)d_in[1];
    float*       out   = (float*)d_out;

    dim3 block(32, 8, 1);
    dim3 grid(IMG / TW, IMG / TH, 16 * 3);   // 4 x 8 x 48 = 1536
    AdaptiveGaussianFilter_66675072303489_kernel<<<grid, block>>>(x, sigma, out);
}

// round 9
// speedup vs baseline: 2.3091x; 1.1173x over previous
#include <cuda_runtime.h>

#define IMG 256
#define TW 64
#define TH 32
#define PR (TH + 6)   // 38 quartet-plane rows

typedef unsigned long long u64;

// ---- packed f32x2 helpers (sm_103a FFMA2 path, PTX-only) ----
__device__ __forceinline__ u64 pk2(float lo, float hi) {
    u64 r; asm("mov.b64 %0, {%1,%2};" : "=l"(r) : "f"(lo), "f"(hi)); return r;
}
__device__ __forceinline__ void upk2(float& lo, float& hi, u64 p) {
    asm("mov.b64 {%0,%1}, %2;" : "=f"(lo), "=f"(hi) : "l"(p));
}
__device__ __forceinline__ u64 f2fma(u64 a, u64 b, u64 c) {
    u64 d; asm("fma.rn.f32x2 %0,%1,%2,%3;" : "=l"(d) : "l"(a), "l"(b), "l"(c)); return d;
}
__device__ __forceinline__ u64 f2mul(u64 a, u64 b) {
    u64 d; asm("mul.rn.f32x2 %0,%1,%2;" : "=l"(d) : "l"(a), "l"(b)); return d;
}
__device__ __forceinline__ u64 f2add(u64 a, u64 b) {
    u64 d; asm("add.rn.f32x2 %0,%1,%2;" : "=l"(d) : "l"(a), "l"(b)); return d;
}
__device__ __forceinline__ float ex2f(float x) {
    float r; asm("ex2.approx.f32 %0, %1;" : "=f"(r) : "f"(x)); return r;
}
__device__ __forceinline__ float rcpf(float x) {
    float r; asm("rcp.approx.f32 %0, %1;" : "=f"(r) : "f"(x)); return r;
}

__device__ __forceinline__ int reflect(int v) {
    v = (v < 0) ? -v : v;
    return (v > IMG - 1) ? 2 * (IMG - 1) - v : v;
}

__global__ __launch_bounds__(256, 4)
void AdaptiveGaussianFilter_66675072303489_kernel(
    const float* __restrict__ x,
    const float* __restrict__ sigma,
    float* __restrict__ out)
{
    // Planar quartet planes: m=w0, a=w-1+w+1, b=w-2+w+2, c=w-3+w+3 (38.9 KB)
    __shared__ __align__(16) float qm[PR][TW];
    __shared__ __align__(16) float qa[PR][TW];
    __shared__ __align__(16) float qb[PR][TW];
    __shared__ __align__(16) float qc[PR][TW];

    const int ch = blockIdx.z;
    const int x0 = blockIdx.x * TW;
    const int y0 = blockIdx.y * TH;

    const float* xc = x     + (size_t)ch * IMG * IMG;
    const float* sc = sigma + (size_t)ch * IMG * IMG;
    float*       oc = out   + (size_t)ch * IMG * IMG;

    const int tx  = threadIdx.x;
    const int ty  = threadIdx.y;
    const int tid = ty * 32 + tx;

    const int c2  = tx << 1;                 // 0..62
    const int ly0 = ty << 2;                 // 0..28

    // Preload all 4 sigma pairs (LDG latency hides under pass-1 fill)
    const float* sp = sc + (y0 + ly0) * IMG + x0 + c2;
    u64 sg[4];
    sg[0] = *(const u64*)(sp);
    sg[1] = *(const u64*)(sp + IMG);
    sg[2] = *(const u64*)(sp + 2 * IMG);
    sg[3] = *(const u64*)(sp + 3 * IMG);

    // ---- Pass 1: build quartet planes straight from gmem ----
    const bool interior = (blockIdx.x != 0) & (blockIdx.x != 3) &
                          (blockIdx.y != 0) & (blockIdx.y != 7);
    #pragma unroll
    for (int it = 0; it < 3; it++) {
        int idx = tid + it * 256;
        if (idx < PR * 16) {                 // 38 rows x 16 strips of 4 cols
            int r  = idx >> 4;
            int c0 = (idx & 15) << 2;
            float w[10];                     // x[x0+c0-3 .. x0+c0+6]
            if (interior) {
                const float* src = xc + (y0 + r - 3) * IMG + (x0 + c0 - 3);
                #pragma unroll
                for (int i = 0; i < 10; i++) w[i] = src[i];
            } else {
                const float* srow = xc + reflect(y0 + r - 3) * IMG;
                #pragma unroll
                for (int i = 0; i < 10; i++) w[i] = srow[reflect(x0 + c0 - 3 + i)];
            }
            *(float4*)&qm[r][c0] = make_float4(w[3], w[4], w[5], w[6]);
            *(float4*)&qa[r][c0] = make_float4(w[2]+w[4], w[3]+w[5], w[4]+w[6], w[5]+w[7]);
            *(float4*)&qb[r][c0] = make_float4(w[1]+w[5], w[2]+w[6], w[3]+w[7], w[4]+w[8]);
            *(float4*)&qc[r][c0] = make_float4(w[0]+w[6], w[1]+w[7], w[2]+w[8], w[3]+w[9]);
        }
    }

    // ---- Exp chains for all 4 output rows BEFORE the barrier (MUFU hidden) ----
    const u64 NHL = pk2(-0.72134752f, -0.72134752f);   // -0.5*log2(e)
    u64 t[4], t4[4], t9[4];
    #pragma unroll
    for (int k = 0; k < 4; k++) {
        u64 z = f2mul(sg[k], sg[k]);
        z = f2mul(z, NHL);
        float zl, zh; upk2(zl, zh, z);
        t[k]  = pk2(ex2f(zl), ex2f(zh));
        u64 t2 = f2mul(t[k], t[k]);
        t4[k] = f2mul(t2, t2);
        t9[k] = f2mul(f2mul(t4[k], t4[k]), t[k]);
    }
    __syncthreads();

    // ---- Pass 2: stream 10 window rows; 4 packed accumulators ----
    u64 acc[4];
    #pragma unroll
    for (int w = -3; w <= 6; w++) {
        const int prow = ly0 + w + 3;        // 0..37 within planes
        const u64 qm_ = *(const u64*)&qm[prow][c2];
        const u64 qa_ = *(const u64*)&qa[prow][c2];
        const u64 qb_ = *(const u64*)&qb[prow][c2];
        const u64 qc_ = *(const u64*)&qc[prow][c2];
        #pragma unroll
        for (int k = 0; k < 4; k++) {
            const int d = (w > k) ? (w - k) : (k - w);
            if (d > 3) continue;
            u64 h = f2fma(t[k],  qa_, qm_);
            h     = f2fma(t4[k], qb_, h);
            h     = f2fma(t9[k], qc_, h);
            if (w == k - 3)     acc[k] = f2mul(t9[k], h);      // first contribution
            else if (d == 3)    acc[k] = f2fma(t9[k], h, acc[k]);
            else if (d == 2)    acc[k] = f2fma(t4[k], h, acc[k]);
            else if (d == 1)    acc[k] = f2fma(t[k],  h, acc[k]);
            else                acc[k] = f2add(acc[k], h);
        }
    }

    // ---- Epilogue: normalize and store ----
    const u64 TWO2 = pk2(2.0f, 2.0f);
    const u64 ONE2 = pk2(1.0f, 1.0f);
    float* op = oc + (y0 + ly0) * IMG + x0 + c2;
    #pragma unroll
    for (int k = 0; k < 4; k++) {
        u64 S  = f2fma(TWO2, f2add(f2add(t[k], t4[k]), t9[k]), ONE2);
        u64 SS = f2mul(S, S);
        float sl, sh; upk2(sl, sh, SS);
        float al, ah; upk2(al, ah, acc[k]);
        *(u64*)(op + k * IMG) = pk2(al * rcpf(sl), ah * rcpf(sh));
    }
}

extern "C" void kernel_launch(void* const* d_in, const int* in_sizes, int n_in,
                              void* d_out, int out_size)
{
    const float* x     = (const float*)d_in[0];
    const float* sigma = (const float*)d_in[1];
    float*       out   = (float*)d_out;

    dim3 block(32, 8, 1);
    dim3 grid(IMG / TW, IMG / TH, 16 * 3);   // 4 x 8 x 48 = 1536
    AdaptiveGaussianFilter_66675072303489_kernel<<<grid, block>>>(x, sigma, out);
}